// round 1
// baseline (speedup 1.0000x reference)
#include <cuda_runtime.h>
#include <math_constants.h>

// VerticalLinePool: out[b,c,h,w] = max_{h' >= h} x[b,c,h',w]
// x shape (8, 128, 256, 256) fp32, NCHW contiguous.
// One thread per (b,c, w/4) column of float4; scan h bottom-up with running max.

#define H_DIM 256
#define W4    64            // W / 4 float4s per row
#define NITEMS (8 * 128 * W4)  // 65536 float4-columns

__global__ __launch_bounds__(64) void vertical_line_pool_kernel(
    const float4* __restrict__ x, float4* __restrict__ out)
{
    unsigned int t = blockIdx.x * 64u + threadIdx.x;   // 0 .. NITEMS-1
    unsigned int bc = t >> 6;          // which (b,c) plane
    unsigned int w4 = t & 63u;         // which float4 within a row

    size_t base = (size_t)bc * (H_DIM * W4) + w4;      // element (h=0) of this column
    const float4* __restrict__ xp = x + base;
    float4* __restrict__ op = out + base;

    float4 m = make_float4(-CUDART_INF_F, -CUDART_INF_F, -CUDART_INF_F, -CUDART_INF_F);

    // Scan from bottom (h = H-1) to top (h = 0). 256 iterations, unroll 8:
    // 8 independent LDG.128 per group -> MLP to cover DRAM latency.
    #pragma unroll 8
    for (int h = H_DIM - 1; h >= 0; --h) {
        float4 v = xp[(size_t)h * W4];
        m.x = fmaxf(m.x, v.x);
        m.y = fmaxf(m.y, v.y);
        m.z = fmaxf(m.z, v.z);
        m.w = fmaxf(m.w, v.w);
        op[(size_t)h * W4] = m;
    }
}

extern "C" void kernel_launch(void* const* d_in, const int* in_sizes, int n_in,
                              void* d_out, int out_size)
{
    const float4* x = (const float4*)d_in[0];
    float4* out = (float4*)d_out;

    dim3 grid(NITEMS / 64);   // 1024 blocks
    dim3 block(64);
    vertical_line_pool_kernel<<<grid, block>>>(x, out);
}